// round 15
// baseline (speedup 1.0000x reference)
#include <cuda_runtime.h>
#include <cuda_fp16.h>
#include <math.h>
#include <stdint.h>

// Problem dims
#define Gn   128
#define Sn   32
#define Pn   16
#define Dn   768
#define Cn   256
#define NHn  4
#define OUTn 7
#define GP   2048      // G*P
#define H3   768       // 3*C
#define HO   1024      // NH*C

typedef unsigned long long ull;
typedef __half hf;

// ---------------- device scratch ----------------
__device__ float d_mem   [Sn * GP * Cn];
__device__ float d_hrun  [GP * Cn];
__device__ float d_gh2   [GP * H3];        // interleaved gate layout, incl. bhh
__device__ hf    d_hgat  [GP * HO];        // fp16 now
__device__ float d_spWeff[Dn * Dn];
__device__ float d_gatWT [HO * Dn];
__device__ float d_upWT  [Cn * Dn];
__device__ float d_upgat [HO * Cn];
__device__ float d_Wsp   [Dn * Cn];
__device__ float d_b1    [Dn];
__device__ float d_bg2   [HO];
__device__ float d_bihI  [H3];
__device__ float d_bhhI  [H3];
__device__ unsigned int d_n0cnt[4];        // spkgat completion counters

// fp16 operands (single-precision-rounded)
__device__ hf d_Wih_h[H3 * Cn];
__device__ hf d_Whh_h[H3 * Cn];
__device__ hf d_ug_h [HO * Cn];
__device__ hf d_Wsp_h[Dn * Cn];
__device__ hf d_gw_h [HO * Dn];
__device__ hf d_xb_h [GP * Dn];
__device__ hf d_hr_h [GP * Cn];
__device__ hf d_hn_h [GP * Cn];
__device__ hf d_m_h  [GP * Cn];
__device__ hf d_spk_h[Gn * Dn];

// ---------------- f32x2 helpers (fp32 precompute GEMM) ----------------
__device__ __forceinline__ ull pack2(float x) {
    ull r; asm("mov.b64 %0, {%1, %1};" : "=l"(r) : "f"(x)); return r;
}
__device__ __forceinline__ void ffma2(ull &acc, ull a, ull b) {
    asm("fma.rn.f32x2 %0, %1, %2, %0;" : "+l"(acc) : "l"(a), "l"(b));
}
__device__ __forceinline__ float2 unpack2(ull v) {
    float2 r; asm("mov.b64 {%0, %1}, %2;" : "=f"(r.x), "=f"(r.y) : "l"(v));
    return r;
}

// ---------------- HMMA / cp.async helpers ----------------
__device__ __forceinline__ uint32_t s2u(const void* p) {
    uint32_t a;
    asm("{ .reg .u64 t; cvta.to.shared.u64 t, %1; cvt.u32.u64 %0, t; }"
        : "=r"(a) : "l"(p));
    return a;
}
__device__ __forceinline__ void cpa16(uint32_t dst, const void* src) {
    asm volatile("cp.async.cg.shared.global [%0], [%1], 16;"
                 :: "r"(dst), "l"(src));
}
__device__ __forceinline__ void cp_commit() {
    asm volatile("cp.async.commit_group;" ::: "memory");
}
__device__ __forceinline__ void cp_wait0() {
    asm volatile("cp.async.wait_group 0;" ::: "memory");
}
__device__ __forceinline__ void cp_wait1() {
    asm volatile("cp.async.wait_group 1;" ::: "memory");
}
#define LDSM_X4(r0, r1, r2, r3, addr) \
    asm volatile("ldmatrix.sync.aligned.m8n8.x4.shared.b16 {%0,%1,%2,%3}, [%4];" \
        : "=r"(r0), "=r"(r1), "=r"(r2), "=r"(r3) : "r"(addr))
#define MMA16816(d, a, b) \
    asm volatile("mma.sync.aligned.m16n8k16.row.col.f32.f16.f16.f32 " \
        "{%0,%1,%2,%3}, {%4,%5,%6,%7}, {%8,%9}, {%0,%1,%2,%3};" \
        : "+f"((d)[0]), "+f"((d)[1]), "+f"((d)[2]), "+f"((d)[3]) \
        : "r"((a)[0]), "r"((a)[1]), "r"((a)[2]), "r"((a)[3]), \
          "r"((b)[0]), "r"((b)[1]))

__device__ __forceinline__ float sigm(float x) { return 1.f / (1.f + expf(-x)); }

// ============ 128x128 HMMA tile body (cp.async 3-stage ring) ==============
// stage layout: A [0,8K) | B [8K,16K); stride 16K
#define MM_DSM 49152
__device__ __forceinline__ void g128_issue(
    uint32_t sb, int stage, int t, int row0, int col0,
    const hf* __restrict__ Ah, int lda, const hf* __restrict__ Bh, int ldb)
{
    const int k0 = stage << 5;
    const uint32_t nb = (uint32_t)(stage % 3) * 16384u;
#pragma unroll
    for (int j = 0; j < 4; j++) {
        const int tile = j >> 1;                 // 0=A, 1=B
        const int idx = ((j & 1) << 8) + t;
        const int row = idx >> 2, kq = idx & 3;
        const hf* src = tile ? Bh : Ah;
        const int rb = tile ? col0 : row0;
        const int ld = tile ? ldb : lda;
        uint32_t off = nb + (uint32_t)tile * 8192u + (uint32_t)(kq >> 1) * 4096u
                     + (uint32_t)row * 32u + (uint32_t)(kq & 1) * 16u;
        cpa16(sb + off, src + (size_t)(rb + row) * ld + k0 + kq * 8);
    }
    cp_commit();
}

__device__ __forceinline__ void gemm128_tile(
    char* smraw, int row0, int col0,
    const hf* __restrict__ Ah, int lda,
    const hf* __restrict__ Bh, int ldb,
    const float* __restrict__ bias,
    float* __restrict__ C, int ldc,
    hf* __restrict__ Cf16, int ldcf, int K)
{
    const int t = threadIdx.x;
    const int wid = t >> 5, lane = t & 31;
    const int wm = (wid >> 2) * 64;
    const int wn = (wid & 3) * 32;
    const int i8 = lane & 7, sel = lane >> 3;
    const uint32_t sb = s2u(smraw);

    float acc[4][4][4];
#pragma unroll
    for (int mt = 0; mt < 4; mt++)
#pragma unroll
        for (int nt = 0; nt < 4; nt++)
#pragma unroll
            for (int q = 0; q < 4; q++) acc[mt][nt][q] = 0.f;

    uint32_t aoff[4], boff[2];
#pragma unroll
    for (int mt = 0; mt < 4; mt++)
        aoff[mt] = (uint32_t)(wm + mt * 16 + i8 + ((sel & 1) << 3)) * 32u
                 + (uint32_t)((sel >> 1) << 4);
#pragma unroll
    for (int ng = 0; ng < 2; ng++)
        boff[ng] = (uint32_t)(wn + ng * 16 + i8 + ((sel >> 1) << 3)) * 32u
                 + (uint32_t)((sel & 1) << 4);

    const int nstage = K >> 5;

    g128_issue(sb, 0, t, row0, col0, Ah, lda, Bh, ldb);
    if (nstage > 1) {
        g128_issue(sb, 1, t, row0, col0, Ah, lda, Bh, ldb);
        cp_wait1();
    } else {
        cp_wait0();
    }
    __syncthreads();

    for (int s = 0; s < nstage; s++) {
        if (s + 2 < nstage)
            g128_issue(sb, s + 2, t, row0, col0, Ah, lda, Bh, ldb);
        const uint32_t bufb = (uint32_t)(s % 3) * 16384u;
#pragma unroll
        for (int k16 = 0; k16 < 2; k16++) {
            const uint32_t ab = sb + bufb + (uint32_t)k16 * 4096u;
            const uint32_t bb = ab + 8192u;
            uint32_t ah[4][4], bh[4][2];
#pragma unroll
            for (int mt = 0; mt < 4; mt++)
                LDSM_X4(ah[mt][0], ah[mt][1], ah[mt][2], ah[mt][3], ab + aoff[mt]);
#pragma unroll
            for (int ng = 0; ng < 2; ng++)
                LDSM_X4(bh[ng*2][0], bh[ng*2][1], bh[ng*2+1][0], bh[ng*2+1][1],
                        bb + boff[ng]);
#pragma unroll
            for (int mt = 0; mt < 4; mt++)
#pragma unroll
                for (int nt = 0; nt < 4; nt++)
                    MMA16816(acc[mt][nt], ah[mt], bh[nt]);
        }
        if (s + 1 < nstage) {
            if (s + 2 < nstage) cp_wait1(); else cp_wait0();
            __syncthreads();
        }
    }

    const int l4 = lane >> 2, l2 = (lane & 3) * 2;
#pragma unroll
    for (int mt = 0; mt < 4; mt++) {
#pragma unroll
        for (int nt = 0; nt < 4; nt++) {
            int r = row0 + wm + mt * 16 + l4;
            int c = col0 + wn + nt * 8 + l2;
            float v0 = acc[mt][nt][0], v1 = acc[mt][nt][1];
            float v2 = acc[mt][nt][2], v3 = acc[mt][nt][3];
            if (bias) {
                float b0 = bias[c], b1v = bias[c + 1];
                v0 += b0; v1 += b1v; v2 += b0; v3 += b1v;
            }
            if (C) {
                *(float2*)(C + (size_t)r * ldc + c)       = make_float2(v0, v1);
                *(float2*)(C + (size_t)(r + 8) * ldc + c) = make_float2(v2, v3);
            }
            if (Cf16) {
                *(__half2*)(Cf16 + (size_t)r * ldcf + c) =
                    __halves2half2(__float2half_rn(v0), __float2half_rn(v1));
                *(__half2*)(Cf16 + (size_t)(r + 8) * ldcf + c) =
                    __halves2half2(__float2half_rn(v2), __float2half_rn(v3));
            }
        }
    }
}

// ============ 32x64 skinny HMMA tile body (cp.async 2-stage) ==============
// stage: A [0,2K) | B [2K,6K); stride 6144
__device__ __forceinline__ void skinny_tile(
    char* smraw, int row0, int col0,
    const hf* __restrict__ Ah, int lda,
    const hf* __restrict__ Bh, int ldb,
    const float* __restrict__ bias,
    float* __restrict__ C, int ldc,
    hf* __restrict__ Ch, int ldch,
    int K, int relu)
{
    const int t = threadIdx.x;
    const int wid = t >> 5, lane = t & 31;
    const int wm = (wid >> 2) * 16;
    const int wn = (wid & 3) * 16;
    const int i8 = lane & 7, sel = lane >> 3;
    const uint32_t sb = s2u(smraw);

    float acc[2][4];
#pragma unroll
    for (int nt = 0; nt < 2; nt++)
#pragma unroll
        for (int q = 0; q < 4; q++) acc[nt][q] = 0.f;

    const uint32_t aoff = (uint32_t)(wm + i8 + ((sel & 1) << 3)) * 32u
                        + (uint32_t)((sel >> 1) << 4);
    const uint32_t boff = (uint32_t)(wn + i8 + ((sel >> 1) << 3)) * 32u
                        + (uint32_t)((sel & 1) << 4);

    const int nstage = K >> 5;

    {
        if (t < 128) {
            const int ra = t >> 2, ka = t & 3;
            uint32_t off = (uint32_t)(ka >> 1) * 1024u
                         + (uint32_t)ra * 32u + (uint32_t)(ka & 1) * 16u;
            cpa16(sb + off, Ah + (size_t)(row0 + ra) * lda + ka * 8);
        }
        const int rbr = (t >> 2) & 63, kb = t & 3;
        uint32_t off2 = 2048u + (uint32_t)(kb >> 1) * 2048u
                      + (uint32_t)rbr * 32u + (uint32_t)(kb & 1) * 16u;
        cpa16(sb + off2, Bh + (size_t)(col0 + rbr) * ldb + kb * 8);
    }
    cp_commit();
    cp_wait0();
    __syncthreads();

    int buf = 0;
    for (int s = 0; s < nstage; s++) {
        const bool more = (s + 1) < nstage;
        if (more) {
            const int k0 = (s + 1) << 5;
            const uint32_t nb = (uint32_t)(buf ^ 1) * 6144u;
            if (t < 128) {
                const int ra = t >> 2, ka = t & 3;
                uint32_t off = nb + (uint32_t)(ka >> 1) * 1024u
                             + (uint32_t)ra * 32u + (uint32_t)(ka & 1) * 16u;
                cpa16(sb + off, Ah + (size_t)(row0 + ra) * lda + k0 + ka * 8);
            }
            const int rbr = (t >> 2) & 63, kb = t & 3;
            uint32_t off2 = nb + 2048u + (uint32_t)(kb >> 1) * 2048u
                          + (uint32_t)rbr * 32u + (uint32_t)(kb & 1) * 16u;
            cpa16(sb + off2, Bh + (size_t)(col0 + rbr) * ldb + k0 + kb * 8);
            cp_commit();
        }
#pragma unroll
        for (int k16 = 0; k16 < 2; k16++) {
            const uint32_t base = sb + (uint32_t)buf * 6144u;
            const uint32_t abh = base + (uint32_t)k16 * 1024u;
            const uint32_t bbh = base + 2048u + (uint32_t)k16 * 2048u;
            uint32_t ah[4], bh[2][2];
            LDSM_X4(ah[0], ah[1], ah[2], ah[3], abh + aoff);
            LDSM_X4(bh[0][0], bh[0][1], bh[1][0], bh[1][1], bbh + boff);
#pragma unroll
            for (int nt = 0; nt < 2; nt++)
                MMA16816(acc[nt], ah, bh[nt]);
        }
        cp_wait0();
        __syncthreads();
        buf ^= 1;
    }

    const int l4 = lane >> 2, l2 = (lane & 3) * 2;
#pragma unroll
    for (int nt = 0; nt < 2; nt++) {
        int r = row0 + wm + l4;
        int c = col0 + wn + nt * 8 + l2;
        float v0 = acc[nt][0], v1 = acc[nt][1];
        float v2 = acc[nt][2], v3 = acc[nt][3];
        if (bias) {
            float b0 = bias[c], b1v = bias[c + 1];
            v0 += b0; v1 += b1v; v2 += b0; v3 += b1v;
        }
        if (relu) {
            v0 = fmaxf(v0, 0.f); v1 = fmaxf(v1, 0.f);
            v2 = fmaxf(v2, 0.f); v3 = fmaxf(v3, 0.f);
        }
        if (C) {
            *(float2*)(C + (size_t)r * ldc + c)       = make_float2(v0, v1);
            *(float2*)(C + (size_t)(r + 8) * ldc + c) = make_float2(v2, v3);
        }
        if (Ch) {
            *(__half2*)(Ch + (size_t)r * ldch + c) =
                __halves2half2(__float2half_rn(v0), __float2half_rn(v1));
            *(__half2*)(Ch + (size_t)(r + 8) * ldch + c) =
                __halves2half2(__float2half_rn(v2), __float2half_rn(v3));
        }
    }
}

// ============ GAT attention epilogue body (reads fp16 hgat) ===============
__device__ __forceinline__ void gat_epi_body(
    int g,
    const float* __restrict__ att_src, const float* __restrict__ att_dst,
    const float* __restrict__ gat_b, float* __restrict__ mout)
{
    __shared__ float es[Pn][NHn], ed[Pn][NHn];
    __shared__ float w0s[Pn][NHn], w1s[Pn][NHn];
    __shared__ float h0[HO];
    int t = threadIdx.x, warp = t >> 5, lane = t & 31;
    const hf* hbase = d_hgat + (size_t)g * Pn * HO;

    for (int i = t; i < HO; i += 256) h0[i] = __half2float(hbase[i]);

    for (int it = 0; it < 16; it++) {
        int job = warp + it * 8;
        int p = job >> 3, nh = (job >> 1) & 3, which = job & 1;
        const hf* hrow = hbase + (size_t)p * HO + nh * 256;
        const float* att  = (which ? att_dst : att_src) + nh * 256;
        float s = 0.f;
        for (int c = lane; c < 256; c += 32) s += __half2float(hrow[c]) * att[c];
#pragma unroll
        for (int off = 16; off; off >>= 1) s += __shfl_down_sync(0xffffffffu, s, off);
        if (lane == 0) { if (which) ed[p][nh] = s; else es[p][nh] = s; }
    }
    __syncthreads();
    if (t < 64) {
        int p = t >> 2, nh = t & 3;
        float a = es[0][nh] + ed[p][nh]; a = (a > 0.f) ? a : 0.2f * a;
        float b = es[p][nh] + ed[p][nh]; b = (b > 0.f) ? b : 0.2f * b;
        float mx = fmaxf(a, b);
        float ea = expf(a - mx), eb = expf(b - mx);
        float inv = 1.f / (ea + eb);
        w0s[p][nh] = ea * inv; w1s[p][nh] = eb * inv;
    }
    __syncthreads();
    int c = t;
    for (int p = 0; p < Pn; p++) {
        const hf* hrow = hbase + (size_t)p * HO;
        float acc = 0.f;
#pragma unroll
        for (int nh = 0; nh < NHn; nh++)
            acc += w0s[p][nh] * h0[nh * 256 + c]
                 + w1s[p][nh] * __half2float(hrow[nh * 256 + c]);
        float v = acc * 0.25f + gat_b[c];
        size_t oi = (size_t)(g * Pn + p) * Cn + c;
        mout[oi] = v;
        d_m_h[oi] = __float2half_rn(v);
    }
}

// ---------------- kernel wrappers ----------------
__global__ void __launch_bounds__(256)
mma_gemm(const hf* __restrict__ Ah, int lda, const hf* __restrict__ Bh, int ldb,
         const float* __restrict__ bias, float* __restrict__ C, int ldc,
         hf* __restrict__ Cf16, int ldcf, int K)
{
    extern __shared__ char smraw[];
    gemm128_tile(smraw, blockIdx.y * 128, blockIdx.x * 128,
                 Ah, lda, Bh, ldb, bias, C, ldc, Cf16, ldcf, K);
}

__global__ void __launch_bounds__(256)
k_gat_epi(const float* __restrict__ att_src, const float* __restrict__ att_dst,
          const float* __restrict__ gat_b, float* __restrict__ mout)
{
    gat_epi_body(blockIdx.x, att_src, att_dst, gat_b, mout);
}

// combined: blocks [0,128) hgat tiles (fp16 out), [128,176) spk skinny tiles
__global__ void __launch_bounds__(256)
k_spk_hgat(const hf* __restrict__ hn_h, const hf* __restrict__ ug_h,
           const float* __restrict__ bg2, hf* __restrict__ hgat,
           const hf* __restrict__ Wsp_h, const float* __restrict__ b1,
           hf* __restrict__ spk_h)
{
    extern __shared__ char smraw[];
    if (blockIdx.x < 128) {
        gemm128_tile(smraw, (blockIdx.x >> 3) * 128, (blockIdx.x & 7) * 128,
                     hn_h, Cn, ug_h, Cn, bg2, nullptr, 0, hgat, HO, Cn);
    } else {
        int b = blockIdx.x - 128;                 // 0..47 -> 12 cols x 4 rows
        skinny_tile(smraw, (b / 12) * 32, (b % 12) * 64,
                    hn_h, Pn * Cn, Wsp_h, Cn, b1,
                    nullptr, 0, spk_h, Dn, Cn, 1);
    }
}

// merged spkgat + epilogue: blocks [0,64) spkgat tiles + flag; [64,192) epi
__global__ void __launch_bounds__(256)
k_spkgat_epi(const hf* __restrict__ spk_h, const hf* __restrict__ gw_h,
             const float* __restrict__ att_src, const float* __restrict__ att_dst,
             const float* __restrict__ gat_b, float* __restrict__ mout,
             hf* __restrict__ hgat, int step)
{
    extern __shared__ char smraw[];
    if (blockIdx.x < 64) {
        int b = blockIdx.x;                       // rowgroup = b>>4 (32 graphs)
        skinny_tile(smraw, (b >> 4) * 32, (b & 15) * 64,
                    spk_h, Dn, gw_h, Dn, nullptr,
                    nullptr, 0, hgat, Pn * HO, Dn, 0);
        __threadfence();
        __syncthreads();
        if (threadIdx.x == 0)
            atomicAdd(&d_n0cnt[b >> 4], 1u);
    } else {
        int g = blockIdx.x - 64;
        if (threadIdx.x == 0) {
            unsigned int tgt = 16u * (unsigned int)step;
            while (*(volatile unsigned int*)&d_n0cnt[g >> 5] < tgt)
                __nanosleep(32);
            __threadfence();
        }
        __syncthreads();
        gat_epi_body(g, att_src, att_dst, gat_b, mout);
    }
}

// ============ fused GEMM+GRU: tile 128x96, 3-stage cp.async ring ==========
// stage: A [0,8K) | B [8K,14336); stride 14336. Epilogue st needs 51200 B.
#define GRU_DSM 51200
__device__ __forceinline__ void gru_issue(
    uint32_t sb, int stage, int t, int row0, int col0,
    const hf* __restrict__ Ah, int lda, const hf* __restrict__ Bh)
{
    const int k0 = stage << 5;
    const uint32_t nb = (uint32_t)(stage % 3) * 14336u;
#pragma unroll
    for (int j = 0; j < 2; j++) {
        const int idx = (j << 8) + t;
        const int row = idx >> 2, kq = idx & 3;
        uint32_t off = nb + (uint32_t)(kq >> 1) * 4096u
                     + (uint32_t)row * 32u + (uint32_t)(kq & 1) * 16u;
        cpa16(sb + off, Ah + (size_t)(row0 + row) * lda + k0 + kq * 8);
    }
#pragma unroll
    for (int j = 0; j < 2; j++) {
        const int idx = (j << 8) + t;
        if (idx < 384) {
            const int row = idx >> 2, kq = idx & 3;
            uint32_t off = nb + 8192u + (uint32_t)(kq >> 1) * 3072u
                         + (uint32_t)row * 32u + (uint32_t)(kq & 1) * 16u;
            cpa16(sb + off, Bh + (size_t)(col0 + row) * Cn + k0 + kq * 8);
        }
    }
    cp_commit();
}

__global__ void __launch_bounds__(256)
mma_gru(const hf* __restrict__ Ah, int lda, const hf* __restrict__ Bh,
        const float* __restrict__ ghOld,
        float* __restrict__ ghOut,
        float* __restrict__ hrun,
        hf* __restrict__ oH, int mode)
{
    extern __shared__ char smraw[];
    const int t = threadIdx.x;
    const int wid = t >> 5, lane = t & 31;
    const int row0 = blockIdx.y * 128;
    const int col0 = blockIdx.x * 96;
    const int wm = (wid & 3) * 32;
    const int wn = (wid >> 2) * 48;
    const int i8 = lane & 7, sel = lane >> 3;
    const uint32_t sb = s2u(smraw);

    float acc[2][6][4];
#pragma unroll
    for (int mt = 0; mt < 2; mt++)
#pragma unroll
        for (int nt = 0; nt < 6; nt++)
#pragma unroll
            for (int q = 0; q < 4; q++) acc[mt][nt][q] = 0.f;

    uint32_t aoff[2], boff[3];
#pragma unroll
    for (int mt = 0; mt < 2; mt++)
        aoff[mt] = (uint32_t)(wm + mt * 16 + i8 + ((sel & 1) << 3)) * 32u
                 + (uint32_t)((sel >> 1) << 4);
#pragma unroll
    for (int ng = 0; ng < 3; ng++)
        boff[ng] = (uint32_t)(wn + ng * 16 + i8 + ((sel >> 1) << 3)) * 32u
                 + (uint32_t)((sel & 1) << 4);

    gru_issue(sb, 0, t, row0, col0, Ah, lda, Bh);
    gru_issue(sb, 1, t, row0, col0, Ah, lda, Bh);
    cp_wait1();
    __syncthreads();

    for (int s = 0; s < 8; s++) {              // K=256, BK=32
        if (s + 2 < 8)
            gru_issue(sb, s + 2, t, row0, col0, Ah, lda, Bh);
        const uint32_t bufb = (uint32_t)(s % 3) * 14336u;
#pragma unroll
        for (int k16 = 0; k16 < 2; k16++) {
            const uint32_t abh = sb + bufb + (uint32_t)k16 * 4096u;
            const uint32_t bbh = sb + bufb + 8192u + (uint32_t)k16 * 3072u;
            uint32_t ah[2][4], bh[6][2];
#pragma unroll
            for (int mt = 0; mt < 2; mt++)
                LDSM_X4(ah[mt][0], ah[mt][1], ah[mt][2], ah[mt][3], abh + aoff[mt]);
#pragma unroll
            for (int ng = 0; ng < 3; ng++)
                LDSM_X4(bh[ng*2][0], bh[ng*2][1], bh[ng*2+1][0], bh[ng*2+1][1],
                        bbh + boff[ng]);
#pragma unroll
            for (int mt = 0; mt < 2; mt++)
#pragma unroll
                for (int nt = 0; nt < 6; nt++)
                    MMA16816(acc[mt][nt], ah[mt], bh[nt]);
        }
        if (s + 1 < 8) {
            if (s + 2 < 8) cp_wait1(); else cp_wait0();
            __syncthreads();
        }
    }
    __syncthreads();

    // ---- stage accumulator to smem (128 x 96 fp32, stride 100) ----
    float* st = (float*)smraw;
    const int l4 = lane >> 2, l2 = (lane & 3) * 2;
#pragma unroll
    for (int mt = 0; mt < 2; mt++) {
#pragma unroll
        for (int nt = 0; nt < 6; nt++) {
            int r = wm + mt * 16 + l4;
            int c = wn + nt * 8 + l2;
            float v0 = acc[mt][nt][0], v1 = acc[mt][nt][1];
            float v2 = acc[mt][nt][2], v3 = acc[mt][nt][3];
            if (mode == 2) {
                float b0 = d_bhhI[col0 + c], b1v = d_bhhI[col0 + c + 1];
                v0 += b0; v1 += b1v; v2 += b0; v3 += b1v;
                *(float2*)(ghOut + (size_t)(row0 + r) * H3 + col0 + c) =
                    make_float2(v0, v1);
                *(float2*)(ghOut + (size_t)(row0 + r + 8) * H3 + col0 + c) =
                    make_float2(v2, v3);
            }
            *(float2*)(st + r * 100 + c)       = make_float2(v0, v1);
            *(float2*)(st + (r + 8) * 100 + c) = make_float2(v2, v3);
        }
    }
    __syncthreads();

    // ---- GRU epilogue ----
    const int kbase = col0 / 3;
#pragma unroll
    for (int i = 0; i < 16; i++) {
        const int e = (i << 8) + t;
        const int r = e >> 5, kk = e & 31;
        const int grow = row0 + r;
        const int gk = kbase + kk;
        const int cc = kk * 3;
        float a0, a1, a2, g0, g1, g2;
        if (mode == 1) {
            a0 = st[r * 100 + cc + 0] + d_bihI[col0 + cc + 0];
            a1 = st[r * 100 + cc + 1] + d_bihI[col0 + cc + 1];
            a2 = st[r * 100 + cc + 2] + d_bihI[col0 + cc + 2];
            const float* gh = ghOld + (size_t)grow * H3 + col0 + cc;
            g0 = gh[0]; g1 = gh[1]; g2 = gh[2];
        } else {
            a0 = d_bihI[col0 + cc + 0];
            a1 = d_bihI[col0 + cc + 1];
            a2 = d_bihI[col0 + cc + 2];
            g0 = st[r * 100 + cc + 0];
            g1 = st[r * 100 + cc + 1];
            g2 = st[r * 100 + cc + 2];
        }
        float rr = sigm(a0 + g0);
        float zz = sigm(a1 + g1);
        float nn = tanhf(a2 + rr * g2);
        size_t hi = (size_t)grow * Cn + gk;
        float h = (1.f - zz) * nn + zz * hrun[hi];
        if (mode == 1) hrun[hi] = h;
        oH[hi] = __float2half_rn(h);
    }
}

// ---------------- fp32 32x128 GEMM (precompute only) ----------------
__global__ void __launch_bounds__(128)
gemm32(const float* __restrict__ A, const float* __restrict__ B,
       const float* __restrict__ bias, float* __restrict__ Cmat,
       int lda, int ldb, int ldc, int K, int relu)
{
    __shared__ float As[2][16][32];
    __shared__ float Bs[2][16][128];
    const int row0 = blockIdx.y * 32;
    const int col0 = blockIdx.x * 128;
    const int t  = threadIdx.x;
    const int ar = t >> 2;
    const int ak = (t & 3) * 4;
    const int tm = t >> 4;
    const int tn = t & 15;

    ull acc[4][4];
#pragma unroll
    for (int i = 0; i < 4; i++)
#pragma unroll
        for (int j = 0; j < 4; j++) acc[i][j] = 0ull;

    const float* Aptr = A + (size_t)(row0 + ar) * lda + ak;

    {
        float4 av = *(const float4*)(Aptr);
        As[0][ak+0][ar]=av.x; As[0][ak+1][ar]=av.y; As[0][ak+2][ar]=av.z; As[0][ak+3][ar]=av.w;
#pragma unroll
        for (int i2 = 0; i2 < 4; i2++) {
            int idx = t + 128 * i2;
            int br = idx >> 2, bk = (idx & 3) * 4;
            float4 bv = *(const float4*)(B + (size_t)(col0 + br) * ldb + bk);
            Bs[0][bk+0][br]=bv.x; Bs[0][bk+1][br]=bv.y; Bs[0][bk+2][br]=bv.z; Bs[0][bk+3][br]=bv.w;
        }
    }
    __syncthreads();

    int buf = 0;
    for (int k0 = 0; k0 < K; k0 += 16) {
        const bool more = (k0 + 16) < K;
        float4 an; float4 bn[4];
        if (more) {
            an = *(const float4*)(Aptr + k0 + 16);
#pragma unroll
            for (int i2 = 0; i2 < 4; i2++) {
                int idx = t + 128 * i2;
                int br = idx >> 2, bk = (idx & 3) * 4;
                bn[i2] = *(const float4*)(B + (size_t)(col0 + br) * ldb + k0 + 16 + bk);
            }
        }
#pragma unroll
        for (int kk = 0; kk < 16; kk++) {
            float av4[4];
            *(float4*)(av4) = *(const float4*)(&As[buf][kk][tm * 4]);
            ulonglong2 bv0 = *(const ulonglong2*)(&Bs[buf][kk][tn * 4]);
            ulonglong2 bv1 = *(const ulonglong2*)(&Bs[buf][kk][tn * 4 + 64]);
#pragma unroll
            for (int i = 0; i < 4; i++) {
                ull ap = pack2(av4[i]);
                ffma2(acc[i][0], ap, bv0.x);
                ffma2(acc[i][1], ap, bv0.y);
                ffma2(acc[i][2], ap, bv1.x);
                ffma2(acc[i][3], ap, bv1.y);
            }
        }
        if (more) {
            int nb = buf ^ 1;
            As[nb][ak+0][ar]=an.x; As[nb][ak+1][ar]=an.y; As[nb][ak+2][ar]=an.z; As[nb][ak+3][ar]=an.w;
#pragma unroll
            for (int i2 = 0; i2 < 4; i2++) {
                int idx = t + 128 * i2;
                int br = idx >> 2, bk = (idx & 3) * 4;
                Bs[nb][bk+0][br]=bn[i2].x; Bs[nb][bk+1][br]=bn[i2].y;
                Bs[nb][bk+2][br]=bn[i2].z; Bs[nb][bk+3][br]=bn[i2].w;
            }
        }
        __syncthreads();
        buf ^= 1;
    }
#pragma unroll
    for (int i = 0; i < 4; i++) {
        int r = row0 + tm * 4 + i;
        float* crow = Cmat + (size_t)r * ldc;
#pragma unroll
        for (int jp = 0; jp < 4; jp++) {
            int c = col0 + ((jp < 2) ? (tn * 4 + jp * 2) : (64 + tn * 4 + (jp - 2) * 2));
            float2 v = unpack2(acc[i][jp]);
            if (bias) { v.x += bias[c]; v.y += bias[c + 1]; }
            if (relu) { v.x = fmaxf(v.x, 0.f); v.y = fmaxf(v.y, 0.f); }
            *(float2*)(crow + c) = v;
        }
    }
}

// ---------------- elementwise / prep kernels ----------------
__global__ void k_copy_x0(const float* __restrict__ x) {
    int idx = blockIdx.x * 256 + threadIdx.x;
    int n = idx / Dn, d = idx - n * Dn;
    int g = n >> 4, p = n & 15;
    d_xb_h[idx] = __float2half_rn(x[((size_t)g * Sn * Pn + p) * Dn + d]);
}
__global__ void k_zero_hrun() {
    int idx = blockIdx.x * 256 + threadIdx.x;
    d_hrun[idx] = 0.f;
    if (idx < 4) d_n0cnt[idx] = 0u;
}
__global__ void k_bias_il(const float* __restrict__ bih, const float* __restrict__ bhh) {
    int idx = blockIdx.x * 256 + threadIdx.x;
    if (idx < H3) {
        int g = idx / 256, k = idx % 256;
        d_bihI[3 * k + g] = bih[idx];
        d_bhhI[3 * k + g] = bhh[idx];
    }
}
__global__ void k_init_gh2() {
    int idx = blockIdx.x * 256 + threadIdx.x;
    d_gh2[idx] = d_bhhI[idx % H3];
}
__global__ void k_speff(const float* __restrict__ spW) {
    int idx = blockIdx.x * 256 + threadIdx.x;
    int n = idx / Dn, d = idx - n * Dn;
    d_spWeff[idx] = spW[(size_t)n * 1536 + d] + spW[(size_t)n * 1536 + 768 + d];
}
__global__ void k_tr_gat(const float* __restrict__ gw) {
    int idx = blockIdx.x * 256 + threadIdx.x;
    int o = idx / Dn, d = idx - o * Dn;
    float v = gw[(size_t)d * HO + o];
    d_gatWT[idx] = v;
    d_gw_h[idx] = __float2half_rn(v);
}
__global__ void k_tr_up(const float* __restrict__ uw) {
    int idx = blockIdx.x * 256 + threadIdx.x;
    int c = idx / Dn, d = idx - c * Dn;
    d_upWT[idx] = uw[(size_t)d * Cn + c];
}
__global__ void k_b1(const float* __restrict__ sp_b, const float* __restrict__ up_b) {
    int n = blockIdx.x, lane = threadIdx.x;
    float s = 0.f;
    for (int d = lane; d < Dn; d += 32) s += d_spWeff[(size_t)n * Dn + d] * up_b[d];
#pragma unroll
    for (int off = 16; off; off >>= 1) s += __shfl_down_sync(0xffffffffu, s, off);
    if (lane == 0) d_b1[n] = s + sp_b[n];
}
__global__ void k_bg2(const float* __restrict__ up_b) {
    int o = blockIdx.x, lane = threadIdx.x;
    float s = 0.f;
    for (int d = lane; d < Dn; d += 32) s += d_gatWT[(size_t)o * Dn + d] * up_b[d];
#pragma unroll
    for (int off = 16; off; off >>= 1) s += __shfl_down_sync(0xffffffffu, s, off);
    if (lane == 0) d_bg2[o] = s;
}
__global__ void k_roundw(const float* __restrict__ w, hf* __restrict__ hi) {
    int idx = blockIdx.x * 256 + threadIdx.x;
    hi[idx] = __float2half_rn(w[idx]);
}
__global__ void k_roundw_perm(const float* __restrict__ w, hf* __restrict__ hi) {
    int idx = blockIdx.x * 256 + threadIdx.x;
    int row = idx / Cn, col = idx - row * Cn;
    int g = row >> 8, k = row & 255;
    int p = 3 * k + g;
    hi[(size_t)p * Cn + col] = __float2half_rn(w[idx]);
}

// GlobalAttention pool + classifier
__global__ void __launch_bounds__(256)
k_pool(const float* __restrict__ attW, const float* __restrict__ attb,
       const float* __restrict__ clsW, const float* __restrict__ clsb,
       float* __restrict__ out)
{
    int sg = blockIdx.x;
    int s = sg >> 7, g = sg & 127;
    __shared__ float gate[Pn];
    __shared__ float pooled[Cn];
    const float* base = d_mem + ((size_t)s * GP + g * Pn) * Cn;
    int t = threadIdx.x, warp = t >> 5, lane = t & 31;

    for (int p = warp; p < Pn; p += 8) {
        float sum = 0.f;
        for (int c = lane; c < Cn; c += 32) sum += base[p * Cn + c] * attW[c];
#pragma unroll
        for (int off = 16; off; off >>= 1) sum += __shfl_down_sync(0xffffffffu, sum, off);
        if (lane == 0) gate[p] = sum + attb[0];
    }
    __syncthreads();
    if (t == 0) {
        float mx = -1e30f;
        for (int p = 0; p < Pn; p++) mx = fmaxf(mx, gate[p]);
        float den = 0.f, e[Pn];
        for (int p = 0; p < Pn; p++) { e[p] = expf(gate[p] - mx); den += e[p]; }
        float inv = 1.f / den;
        for (int p = 0; p < Pn; p++) gate[p] = e[p] * inv;
    }
    __syncthreads();
    {
        float acc = 0.f;
        for (int p = 0; p < Pn; p++) acc += gate[p] * base[p * Cn + t];
        pooled[t] = acc;
    }
    __syncthreads();
    if (warp < OUTn) {
        float sum = 0.f;
        for (int c = lane; c < Cn; c += 32) sum += pooled[c] * clsW[warp * Cn + c];
#pragma unroll
        for (int off = 16; off; off >>= 1) sum += __shfl_down_sync(0xffffffffu, sum, off);
        if (lane == 0) out[((size_t)g * Sn + s) * OUTn + warp] = sum + clsb[warp];
    }
}

// ---------------- host launcher ----------------
static inline void g32(const float* A, const float* B, const float* b, float* C,
                       int lda, int ldb, int ldc, int M, int N, int K, int relu)
{
    dim3 grid(N / 128, M / 32);
    gemm32<<<grid, 128>>>(A, B, b, C, lda, ldb, ldc, K, relu);
}

extern "C" void kernel_launch(void* const* d_in, const int* in_sizes, int n_in,
                              void* d_out, int out_size)
{
    const float* x      = (const float*)d_in[0];
    const float* gat_W  = (const float*)d_in[1];
    const float* att_src= (const float*)d_in[2];
    const float* att_dst= (const float*)d_in[3];
    const float* gat_b  = (const float*)d_in[4];
    const float* Wih    = (const float*)d_in[5];
    const float* Whh    = (const float*)d_in[6];
    const float* bih    = (const float*)d_in[7];
    const float* bhh    = (const float*)d_in[8];
    const float* up_W   = (const float*)d_in[9];
    const float* up_b   = (const float*)d_in[10];
    const float* sp_W   = (const float*)d_in[11];
    const float* sp_b   = (const float*)d_in[12];
    const float* attW   = (const float*)d_in[13];
    const float* attb   = (const float*)d_in[14];
    const float* clsW   = (const float*)d_in[15];
    const float* clsb   = (const float*)d_in[16];
    float* out = (float*)d_out;

    float *mem, *gh2, *spWeff, *gatWT, *upWT, *upgat, *Wsp, *b1, *bg2, *hrun;
    hf* hgat;
    cudaGetSymbolAddress((void**)&mem,   d_mem);
    cudaGetSymbolAddress((void**)&gh2,   d_gh2);
    cudaGetSymbolAddress((void**)&hgat,  d_hgat);
    cudaGetSymbolAddress((void**)&spWeff,d_spWeff);
    cudaGetSymbolAddress((void**)&gatWT, d_gatWT);
    cudaGetSymbolAddress((void**)&upWT,  d_upWT);
    cudaGetSymbolAddress((void**)&upgat, d_upgat);
    cudaGetSymbolAddress((void**)&Wsp,   d_Wsp);
    cudaGetSymbolAddress((void**)&b1,    d_b1);
    cudaGetSymbolAddress((void**)&bg2,   d_bg2);
    cudaGetSymbolAddress((void**)&hrun,  d_hrun);

    hf *Wih_h, *Whh_h, *ug_h, *Wsp_h, *gw_h, *xb_h;
    hf *hr_h, *hn_h, *m_h, *spk_h;
    cudaGetSymbolAddress((void**)&Wih_h, d_Wih_h);
    cudaGetSymbolAddress((void**)&Whh_h, d_Whh_h);
    cudaGetSymbolAddress((void**)&ug_h,  d_ug_h);
    cudaGetSymbolAddress((void**)&Wsp_h, d_Wsp_h);
    cudaGetSymbolAddress((void**)&gw_h,  d_gw_h);
    cudaGetSymbolAddress((void**)&xb_h,  d_xb_h);
    cudaGetSymbolAddress((void**)&hr_h,  d_hr_h);
    cudaGetSymbolAddress((void**)&hn_h,  d_hn_h);
    cudaGetSymbolAddress((void**)&m_h,   d_m_h);
    cudaGetSymbolAddress((void**)&spk_h, d_spk_h);

    static bool attr_set = false;
    if (!attr_set) {
        cudaFuncSetAttribute(mma_gemm, cudaFuncAttributeMaxDynamicSharedMemorySize, MM_DSM);
        cudaFuncSetAttribute(k_spk_hgat, cudaFuncAttributeMaxDynamicSharedMemorySize, MM_DSM);
        cudaFuncSetAttribute(mma_gru, cudaFuncAttributeMaxDynamicSharedMemorySize, GRU_DSM);
        cudaFuncSetAttribute(k_spkgat_epi, cudaFuncAttributeMaxDynamicSharedMemorySize, 12288);
        attr_set = true;
    }

    // ---- prep ----
    k_copy_x0<<<GP * Dn / 256, 256>>>(x);
    k_zero_hrun<<<GP * Cn / 256, 256>>>();
    k_bias_il<<<3, 256>>>(bih, bhh);
    k_init_gh2<<<GP * H3 / 256, 256>>>();
    k_speff<<<Dn * Dn / 256, 256>>>(sp_W);
    k_tr_gat<<<HO * Dn / 256, 256>>>(gat_W);
    k_tr_up<<<Cn * Dn / 256, 256>>>(up_W);
    k_b1<<<Dn, 32>>>(sp_b, up_b);
    k_bg2<<<HO, 32>>>(up_b);
    g32(gatWT, upWT, nullptr, upgat, Dn, Dn, Cn, HO, Cn, Dn, 0);
    g32(spWeff, upWT, nullptr, Wsp, Dn, Dn, Cn, Dn, Cn, Dn, 0);
    k_roundw_perm<<<H3 * Cn / 256, 256>>>(Wih, Wih_h);
    k_roundw_perm<<<H3 * Cn / 256, 256>>>(Whh, Whh_h);
    k_roundw<<<HO * Cn / 256, 256>>>(upgat, ug_h);
    k_roundw<<<Dn * Cn / 256, 256>>>(Wsp, Wsp_h);

    // ---- m0: GAT on x[:,0] (HMMA, K=768, fp16 hgat out) ----
    mma_gemm<<<dim3(8, 16), 256, MM_DSM>>>(
        xb_h, Dn, gw_h, Dn, nullptr, nullptr, 0, hgat, HO, Dn);
    k_gat_epi<<<Gn, 256>>>(att_src, att_dst, gat_b, mem);

    // ---- 31 sequential steps (4 launches each) ----
    for (int s = 1; s < Sn; s++) {
        mma_gru<<<dim3(8, 16), 256, GRU_DSM>>>(
            m_h, Cn, Wih_h, gh2, nullptr, hrun, hr_h, 1);
        mma_gru<<<dim3(8, 16), 256, GRU_DSM>>>(
            hr_h, Cn, Whh_h, nullptr, gh2, hrun, hn_h, 2);
        k_spk_hgat<<<176, 256, MM_DSM>>>(
            hn_h, ug_h, bg2, hgat, Wsp_h, b1, spk_h);
        k_spkgat_epi<<<192, 256, 12288>>>(
            spk_h, gw_h, att_src, att_dst, gat_b,
            mem + (size_t)s * GP * Cn, hgat, s);
    }

    // ---- pool + classify ----
    k_pool<<<Sn * Gn, 256>>>(attW, attb, clsW, clsb, out);
    (void)in_sizes; (void)n_in; (void)out_size;
}

// round 16
// speedup vs baseline: 1.0237x; 1.0237x over previous
#include <cuda_runtime.h>
#include <cuda_fp16.h>
#include <math.h>
#include <stdint.h>

// Problem dims
#define Gn   128
#define Sn   32
#define Pn   16
#define Dn   768
#define Cn   256
#define NHn  4
#define OUTn 7
#define GP   2048      // G*P
#define H3   768       // 3*C
#define HO   1024      // NH*C

typedef unsigned long long ull;
typedef __half hf;

// ---------------- device scratch ----------------
__device__ hf    d_mem   [Sn * GP * Cn];   // fp16 memory tensor (all steps)
__device__ float d_hrun  [GP * Cn];
__device__ float d_gh2   [GP * H3];        // interleaved gate layout, incl. bhh
__device__ hf    d_hgat  [GP * HO];        // fp16
__device__ float d_spWeff[Dn * Dn];
__device__ float d_gatWT [HO * Dn];
__device__ float d_upWT  [Cn * Dn];
__device__ float d_upgat [HO * Cn];
__device__ float d_Wsp   [Dn * Cn];
__device__ float d_b1    [Dn];
__device__ float d_bg2   [HO];
__device__ float d_bihI  [H3];
__device__ float d_bhhI  [H3];

// fp16 operands (single-precision-rounded)
__device__ hf d_Wih_h[H3 * Cn];
__device__ hf d_Whh_h[H3 * Cn];
__device__ hf d_ug_h [HO * Cn];
__device__ hf d_Wsp_h[Dn * Cn];
__device__ hf d_gw_h [HO * Dn];
__device__ hf d_xb_h [GP * Dn];
__device__ hf d_hr_h [GP * Cn];
__device__ hf d_hn_h [GP * Cn];
__device__ hf d_spk_h[Gn * Dn];

// ---------------- f32x2 helpers (fp32 precompute GEMM) ----------------
__device__ __forceinline__ ull pack2(float x) {
    ull r; asm("mov.b64 %0, {%1, %1};" : "=l"(r) : "f"(x)); return r;
}
__device__ __forceinline__ void ffma2(ull &acc, ull a, ull b) {
    asm("fma.rn.f32x2 %0, %1, %2, %0;" : "+l"(acc) : "l"(a), "l"(b));
}
__device__ __forceinline__ float2 unpack2(ull v) {
    float2 r; asm("mov.b64 {%0, %1}, %2;" : "=f"(r.x), "=f"(r.y) : "l"(v));
    return r;
}

// ---------------- HMMA / cp.async helpers ----------------
__device__ __forceinline__ uint32_t s2u(const void* p) {
    uint32_t a;
    asm("{ .reg .u64 t; cvta.to.shared.u64 t, %1; cvt.u32.u64 %0, t; }"
        : "=r"(a) : "l"(p));
    return a;
}
__device__ __forceinline__ void cpa16(uint32_t dst, const void* src) {
    asm volatile("cp.async.cg.shared.global [%0], [%1], 16;"
                 :: "r"(dst), "l"(src));
}
__device__ __forceinline__ void cp_commit() {
    asm volatile("cp.async.commit_group;" ::: "memory");
}
__device__ __forceinline__ void cp_wait0() {
    asm volatile("cp.async.wait_group 0;" ::: "memory");
}
__device__ __forceinline__ void cp_wait1() {
    asm volatile("cp.async.wait_group 1;" ::: "memory");
}
#define LDSM_X4(r0, r1, r2, r3, addr) \
    asm volatile("ldmatrix.sync.aligned.m8n8.x4.shared.b16 {%0,%1,%2,%3}, [%4];" \
        : "=r"(r0), "=r"(r1), "=r"(r2), "=r"(r3) : "r"(addr))
#define MMA16816(d, a, b) \
    asm volatile("mma.sync.aligned.m16n8k16.row.col.f32.f16.f16.f32 " \
        "{%0,%1,%2,%3}, {%4,%5,%6,%7}, {%8,%9}, {%0,%1,%2,%3};" \
        : "+f"((d)[0]), "+f"((d)[1]), "+f"((d)[2]), "+f"((d)[3]) \
        : "r"((a)[0]), "r"((a)[1]), "r"((a)[2]), "r"((a)[3]), \
          "r"((b)[0]), "r"((b)[1]))

__device__ __forceinline__ float sigm(float x) { return 1.f / (1.f + expf(-x)); }

// ============ 128x128 HMMA tile body (cp.async 3-stage ring) ==============
// stage layout: A [0,8K) | B [8K,16K); stride 16K
#define MM_DSM 49152
__device__ __forceinline__ void g128_issue(
    uint32_t sb, int stage, int t, int row0, int col0,
    const hf* __restrict__ Ah, int lda, const hf* __restrict__ Bh, int ldb)
{
    const int k0 = stage << 5;
    const uint32_t nb = (uint32_t)(stage % 3) * 16384u;
#pragma unroll
    for (int j = 0; j < 4; j++) {
        const int tile = j >> 1;                 // 0=A, 1=B
        const int idx = ((j & 1) << 8) + t;
        const int row = idx >> 2, kq = idx & 3;
        const hf* src = tile ? Bh : Ah;
        const int rb = tile ? col0 : row0;
        const int ld = tile ? ldb : lda;
        uint32_t off = nb + (uint32_t)tile * 8192u + (uint32_t)(kq >> 1) * 4096u
                     + (uint32_t)row * 32u + (uint32_t)(kq & 1) * 16u;
        cpa16(sb + off, src + (size_t)(rb + row) * ld + k0 + kq * 8);
    }
    cp_commit();
}

__device__ __forceinline__ void gemm128_tile(
    char* smraw, int row0, int col0,
    const hf* __restrict__ Ah, int lda,
    const hf* __restrict__ Bh, int ldb,
    const float* __restrict__ bias,
    float* __restrict__ C, int ldc,
    hf* __restrict__ Cf16, int ldcf, int K)
{
    const int t = threadIdx.x;
    const int wid = t >> 5, lane = t & 31;
    const int wm = (wid >> 2) * 64;
    const int wn = (wid & 3) * 32;
    const int i8 = lane & 7, sel = lane >> 3;
    const uint32_t sb = s2u(smraw);

    float acc[4][4][4];
#pragma unroll
    for (int mt = 0; mt < 4; mt++)
#pragma unroll
        for (int nt = 0; nt < 4; nt++)
#pragma unroll
            for (int q = 0; q < 4; q++) acc[mt][nt][q] = 0.f;

    uint32_t aoff[4], boff[2];
#pragma unroll
    for (int mt = 0; mt < 4; mt++)
        aoff[mt] = (uint32_t)(wm + mt * 16 + i8 + ((sel & 1) << 3)) * 32u
                 + (uint32_t)((sel >> 1) << 4);
#pragma unroll
    for (int ng = 0; ng < 2; ng++)
        boff[ng] = (uint32_t)(wn + ng * 16 + i8 + ((sel >> 1) << 3)) * 32u
                 + (uint32_t)((sel & 1) << 4);

    const int nstage = K >> 5;

    g128_issue(sb, 0, t, row0, col0, Ah, lda, Bh, ldb);
    if (nstage > 1) {
        g128_issue(sb, 1, t, row0, col0, Ah, lda, Bh, ldb);
        cp_wait1();
    } else {
        cp_wait0();
    }
    __syncthreads();

    for (int s = 0; s < nstage; s++) {
        if (s + 2 < nstage)
            g128_issue(sb, s + 2, t, row0, col0, Ah, lda, Bh, ldb);
        const uint32_t bufb = (uint32_t)(s % 3) * 16384u;
#pragma unroll
        for (int k16 = 0; k16 < 2; k16++) {
            const uint32_t ab = sb + bufb + (uint32_t)k16 * 4096u;
            const uint32_t bb = ab + 8192u;
            uint32_t ah[4][4], bh[4][2];
#pragma unroll
            for (int mt = 0; mt < 4; mt++)
                LDSM_X4(ah[mt][0], ah[mt][1], ah[mt][2], ah[mt][3], ab + aoff[mt]);
#pragma unroll
            for (int ng = 0; ng < 2; ng++)
                LDSM_X4(bh[ng*2][0], bh[ng*2][1], bh[ng*2+1][0], bh[ng*2+1][1],
                        bb + boff[ng]);
#pragma unroll
            for (int mt = 0; mt < 4; mt++)
#pragma unroll
                for (int nt = 0; nt < 4; nt++)
                    MMA16816(acc[mt][nt], ah[mt], bh[nt]);
        }
        if (s + 1 < nstage) {
            if (s + 2 < nstage) cp_wait1(); else cp_wait0();
            __syncthreads();
        }
    }

    const int l4 = lane >> 2, l2 = (lane & 3) * 2;
#pragma unroll
    for (int mt = 0; mt < 4; mt++) {
#pragma unroll
        for (int nt = 0; nt < 4; nt++) {
            int r = row0 + wm + mt * 16 + l4;
            int c = col0 + wn + nt * 8 + l2;
            float v0 = acc[mt][nt][0], v1 = acc[mt][nt][1];
            float v2 = acc[mt][nt][2], v3 = acc[mt][nt][3];
            if (bias) {
                float b0 = bias[c], b1v = bias[c + 1];
                v0 += b0; v1 += b1v; v2 += b0; v3 += b1v;
            }
            if (C) {
                *(float2*)(C + (size_t)r * ldc + c)       = make_float2(v0, v1);
                *(float2*)(C + (size_t)(r + 8) * ldc + c) = make_float2(v2, v3);
            }
            if (Cf16) {
                *(__half2*)(Cf16 + (size_t)r * ldcf + c) =
                    __halves2half2(__float2half_rn(v0), __float2half_rn(v1));
                *(__half2*)(Cf16 + (size_t)(r + 8) * ldcf + c) =
                    __halves2half2(__float2half_rn(v2), __float2half_rn(v3));
            }
        }
    }
}

// ============ 32x64 skinny HMMA tile body (cp.async 2-stage) ==============
// stage: A [0,2K) | B [2K,6K); stride 6144
__device__ __forceinline__ void skinny_tile(
    char* smraw, int row0, int col0,
    const hf* __restrict__ Ah, int lda,
    const hf* __restrict__ Bh, int ldb,
    const float* __restrict__ bias,
    float* __restrict__ C, int ldc,
    hf* __restrict__ Ch, int ldch,
    int K, int relu)
{
    const int t = threadIdx.x;
    const int wid = t >> 5, lane = t & 31;
    const int wm = (wid >> 2) * 16;
    const int wn = (wid & 3) * 16;
    const int i8 = lane & 7, sel = lane >> 3;
    const uint32_t sb = s2u(smraw);

    float acc[2][4];
#pragma unroll
    for (int nt = 0; nt < 2; nt++)
#pragma unroll
        for (int q = 0; q < 4; q++) acc[nt][q] = 0.f;

    const uint32_t aoff = (uint32_t)(wm + i8 + ((sel & 1) << 3)) * 32u
                        + (uint32_t)((sel >> 1) << 4);
    const uint32_t boff = (uint32_t)(wn + i8 + ((sel >> 1) << 3)) * 32u
                        + (uint32_t)((sel & 1) << 4);

    const int nstage = K >> 5;

    {
        if (t < 128) {
            const int ra = t >> 2, ka = t & 3;
            uint32_t off = (uint32_t)(ka >> 1) * 1024u
                         + (uint32_t)ra * 32u + (uint32_t)(ka & 1) * 16u;
            cpa16(sb + off, Ah + (size_t)(row0 + ra) * lda + ka * 8);
        }
        const int rbr = (t >> 2) & 63, kb = t & 3;
        uint32_t off2 = 2048u + (uint32_t)(kb >> 1) * 2048u
                      + (uint32_t)rbr * 32u + (uint32_t)(kb & 1) * 16u;
        cpa16(sb + off2, Bh + (size_t)(col0 + rbr) * ldb + kb * 8);
    }
    cp_commit();
    cp_wait0();
    __syncthreads();

    int buf = 0;
    for (int s = 0; s < nstage; s++) {
        const bool more = (s + 1) < nstage;
        if (more) {
            const int k0 = (s + 1) << 5;
            const uint32_t nb = (uint32_t)(buf ^ 1) * 6144u;
            if (t < 128) {
                const int ra = t >> 2, ka = t & 3;
                uint32_t off = nb + (uint32_t)(ka >> 1) * 1024u
                             + (uint32_t)ra * 32u + (uint32_t)(ka & 1) * 16u;
                cpa16(sb + off, Ah + (size_t)(row0 + ra) * lda + k0 + ka * 8);
            }
            const int rbr = (t >> 2) & 63, kb = t & 3;
            uint32_t off2 = nb + 2048u + (uint32_t)(kb >> 1) * 2048u
                          + (uint32_t)rbr * 32u + (uint32_t)(kb & 1) * 16u;
            cpa16(sb + off2, Bh + (size_t)(col0 + rbr) * ldb + k0 + kb * 8);
            cp_commit();
        }
#pragma unroll
        for (int k16 = 0; k16 < 2; k16++) {
            const uint32_t base = sb + (uint32_t)buf * 6144u;
            const uint32_t abh = base + (uint32_t)k16 * 1024u;
            const uint32_t bbh = base + 2048u + (uint32_t)k16 * 2048u;
            uint32_t ah[4], bh[2][2];
            LDSM_X4(ah[0], ah[1], ah[2], ah[3], abh + aoff);
            LDSM_X4(bh[0][0], bh[0][1], bh[1][0], bh[1][1], bbh + boff);
#pragma unroll
            for (int nt = 0; nt < 2; nt++)
                MMA16816(acc[nt], ah, bh[nt]);
        }
        cp_wait0();
        __syncthreads();
        buf ^= 1;
    }

    const int l4 = lane >> 2, l2 = (lane & 3) * 2;
#pragma unroll
    for (int nt = 0; nt < 2; nt++) {
        int r = row0 + wm + l4;
        int c = col0 + wn + nt * 8 + l2;
        float v0 = acc[nt][0], v1 = acc[nt][1];
        float v2 = acc[nt][2], v3 = acc[nt][3];
        if (bias) {
            float b0 = bias[c], b1v = bias[c + 1];
            v0 += b0; v1 += b1v; v2 += b0; v3 += b1v;
        }
        if (relu) {
            v0 = fmaxf(v0, 0.f); v1 = fmaxf(v1, 0.f);
            v2 = fmaxf(v2, 0.f); v3 = fmaxf(v3, 0.f);
        }
        if (C) {
            *(float2*)(C + (size_t)r * ldc + c)       = make_float2(v0, v1);
            *(float2*)(C + (size_t)(r + 8) * ldc + c) = make_float2(v2, v3);
        }
        if (Ch) {
            *(__half2*)(Ch + (size_t)r * ldch + c) =
                __halves2half2(__float2half_rn(v0), __float2half_rn(v1));
            *(__half2*)(Ch + (size_t)(r + 8) * ldch + c) =
                __halves2half2(__float2half_rn(v2), __float2half_rn(v3));
        }
    }
}

// ============ GAT attention epilogue body (fp16 in, fp16 out) =============
__device__ __forceinline__ void gat_epi_body(
    int g,
    const float* __restrict__ att_src, const float* __restrict__ att_dst,
    const float* __restrict__ gat_b, hf* __restrict__ mout)
{
    __shared__ float es[Pn][NHn], ed[Pn][NHn];
    __shared__ float w0s[Pn][NHn], w1s[Pn][NHn];
    __shared__ float h0[HO];
    int t = threadIdx.x, warp = t >> 5, lane = t & 31;
    const hf* hbase = d_hgat + (size_t)g * Pn * HO;

    for (int i = t; i < HO; i += 256) h0[i] = __half2float(hbase[i]);

    for (int it = 0; it < 16; it++) {
        int job = warp + it * 8;
        int p = job >> 3, nh = (job >> 1) & 3, which = job & 1;
        const hf* hrow = hbase + (size_t)p * HO + nh * 256;
        const float* att  = (which ? att_dst : att_src) + nh * 256;
        float s = 0.f;
        for (int c = lane; c < 256; c += 32) s += __half2float(hrow[c]) * att[c];
#pragma unroll
        for (int off = 16; off; off >>= 1) s += __shfl_down_sync(0xffffffffu, s, off);
        if (lane == 0) { if (which) ed[p][nh] = s; else es[p][nh] = s; }
    }
    __syncthreads();
    if (t < 64) {
        int p = t >> 2, nh = t & 3;
        float a = es[0][nh] + ed[p][nh]; a = (a > 0.f) ? a : 0.2f * a;
        float b = es[p][nh] + ed[p][nh]; b = (b > 0.f) ? b : 0.2f * b;
        float mx = fmaxf(a, b);
        float ea = expf(a - mx), eb = expf(b - mx);
        float inv = 1.f / (ea + eb);
        w0s[p][nh] = ea * inv; w1s[p][nh] = eb * inv;
    }
    __syncthreads();
    int c = t;
    for (int p = 0; p < Pn; p++) {
        const hf* hrow = hbase + (size_t)p * HO;
        float acc = 0.f;
#pragma unroll
        for (int nh = 0; nh < NHn; nh++)
            acc += w0s[p][nh] * h0[nh * 256 + c]
                 + w1s[p][nh] * __half2float(hrow[nh * 256 + c]);
        float v = acc * 0.25f + gat_b[c];
        mout[(size_t)(g * Pn + p) * Cn + c] = __float2half_rn(v);
    }
}

// ---------------- kernel wrappers ----------------
__global__ void __launch_bounds__(256)
mma_gemm(const hf* __restrict__ Ah, int lda, const hf* __restrict__ Bh, int ldb,
         const float* __restrict__ bias, float* __restrict__ C, int ldc,
         hf* __restrict__ Cf16, int ldcf, int K)
{
    extern __shared__ char smraw[];
    gemm128_tile(smraw, blockIdx.y * 128, blockIdx.x * 128,
                 Ah, lda, Bh, ldb, bias, C, ldc, Cf16, ldcf, K);
}

__global__ void __launch_bounds__(256)
mma_skinny(const hf* __restrict__ Ah, int lda, const hf* __restrict__ Bh, int ldb,
           const float* __restrict__ bias,
           float* __restrict__ C, int ldc,
           hf* __restrict__ Ch, int ldch, int K, int relu)
{
    extern __shared__ char smraw[];
    skinny_tile(smraw, blockIdx.y * 32, blockIdx.x * 64,
                Ah, lda, Bh, ldb, bias, C, ldc, Ch, ldch, K, relu);
}

__global__ void __launch_bounds__(256)
k_gat_epi(const float* __restrict__ att_src, const float* __restrict__ att_dst,
          const float* __restrict__ gat_b, hf* __restrict__ mout)
{
    gat_epi_body(blockIdx.x, att_src, att_dst, gat_b, mout);
}

// combined: blocks [0,128) hgat tiles (fp16 out), [128,176) spk skinny tiles
__global__ void __launch_bounds__(256)
k_spk_hgat(const hf* __restrict__ hn_h, const hf* __restrict__ ug_h,
           const float* __restrict__ bg2, hf* __restrict__ hgat,
           const hf* __restrict__ Wsp_h, const float* __restrict__ b1,
           hf* __restrict__ spk_h)
{
    extern __shared__ char smraw[];
    if (blockIdx.x < 128) {
        gemm128_tile(smraw, (blockIdx.x >> 3) * 128, (blockIdx.x & 7) * 128,
                     hn_h, Cn, ug_h, Cn, bg2, nullptr, 0, hgat, HO, Cn);
    } else {
        int b = blockIdx.x - 128;                 // 0..47 -> 12 cols x 4 rows
        skinny_tile(smraw, (b / 12) * 32, (b % 12) * 64,
                    hn_h, Pn * Cn, Wsp_h, Cn, b1,
                    nullptr, 0, spk_h, Dn, Cn, 1);
    }
}

// ============ fused GEMM+GRU: tile 128x96, 3-stage cp.async ring ==========
// stage: A [0,8K) | B [8K,14336); stride 14336. Epilogue st needs 51200 B.
#define GRU_DSM 51200
__device__ __forceinline__ void gru_issue(
    uint32_t sb, int stage, int t, int row0, int col0,
    const hf* __restrict__ Ah, int lda, const hf* __restrict__ Bh)
{
    const int k0 = stage << 5;
    const uint32_t nb = (uint32_t)(stage % 3) * 14336u;
#pragma unroll
    for (int j = 0; j < 2; j++) {
        const int idx = (j << 8) + t;
        const int row = idx >> 2, kq = idx & 3;
        uint32_t off = nb + (uint32_t)(kq >> 1) * 4096u
                     + (uint32_t)row * 32u + (uint32_t)(kq & 1) * 16u;
        cpa16(sb + off, Ah + (size_t)(row0 + row) * lda + k0 + kq * 8);
    }
#pragma unroll
    for (int j = 0; j < 2; j++) {
        const int idx = (j << 8) + t;
        if (idx < 384) {
            const int row = idx >> 2, kq = idx & 3;
            uint32_t off = nb + 8192u + (uint32_t)(kq >> 1) * 3072u
                         + (uint32_t)row * 32u + (uint32_t)(kq & 1) * 16u;
            cpa16(sb + off, Bh + (size_t)(col0 + row) * Cn + k0 + kq * 8);
        }
    }
    cp_commit();
}

__global__ void __launch_bounds__(256)
mma_gru(const hf* __restrict__ Ah, int lda, const hf* __restrict__ Bh,
        const float* __restrict__ ghOld,
        float* __restrict__ ghOut,
        float* __restrict__ hrun,
        hf* __restrict__ oH, int mode)
{
    extern __shared__ char smraw[];
    const int t = threadIdx.x;
    const int wid = t >> 5, lane = t & 31;
    const int row0 = blockIdx.y * 128;
    const int col0 = blockIdx.x * 96;
    const int wm = (wid & 3) * 32;
    const int wn = (wid >> 2) * 48;
    const int i8 = lane & 7, sel = lane >> 3;
    const uint32_t sb = s2u(smraw);

    float acc[2][6][4];
#pragma unroll
    for (int mt = 0; mt < 2; mt++)
#pragma unroll
        for (int nt = 0; nt < 6; nt++)
#pragma unroll
            for (int q = 0; q < 4; q++) acc[mt][nt][q] = 0.f;

    uint32_t aoff[2], boff[3];
#pragma unroll
    for (int mt = 0; mt < 2; mt++)
        aoff[mt] = (uint32_t)(wm + mt * 16 + i8 + ((sel & 1) << 3)) * 32u
                 + (uint32_t)((sel >> 1) << 4);
#pragma unroll
    for (int ng = 0; ng < 3; ng++)
        boff[ng] = (uint32_t)(wn + ng * 16 + i8 + ((sel >> 1) << 3)) * 32u
                 + (uint32_t)((sel & 1) << 4);

    gru_issue(sb, 0, t, row0, col0, Ah, lda, Bh);
    gru_issue(sb, 1, t, row0, col0, Ah, lda, Bh);
    cp_wait1();
    __syncthreads();

    for (int s = 0; s < 8; s++) {              // K=256, BK=32
        if (s + 2 < 8)
            gru_issue(sb, s + 2, t, row0, col0, Ah, lda, Bh);
        const uint32_t bufb = (uint32_t)(s % 3) * 14336u;
#pragma unroll
        for (int k16 = 0; k16 < 2; k16++) {
            const uint32_t abh = sb + bufb + (uint32_t)k16 * 4096u;
            const uint32_t bbh = sb + bufb + 8192u + (uint32_t)k16 * 3072u;
            uint32_t ah[2][4], bh[6][2];
#pragma unroll
            for (int mt = 0; mt < 2; mt++)
                LDSM_X4(ah[mt][0], ah[mt][1], ah[mt][2], ah[mt][3], abh + aoff[mt]);
#pragma unroll
            for (int ng = 0; ng < 3; ng++)
                LDSM_X4(bh[ng*2][0], bh[ng*2][1], bh[ng*2+1][0], bh[ng*2+1][1],
                        bbh + boff[ng]);
#pragma unroll
            for (int mt = 0; mt < 2; mt++)
#pragma unroll
                for (int nt = 0; nt < 6; nt++)
                    MMA16816(acc[mt][nt], ah[mt], bh[nt]);
        }
        if (s + 1 < 8) {
            if (s + 2 < 8) cp_wait1(); else cp_wait0();
            __syncthreads();
        }
    }
    __syncthreads();

    // ---- stage accumulator to smem (128 x 96 fp32, stride 100) ----
    float* st = (float*)smraw;
    const int l4 = lane >> 2, l2 = (lane & 3) * 2;
#pragma unroll
    for (int mt = 0; mt < 2; mt++) {
#pragma unroll
        for (int nt = 0; nt < 6; nt++) {
            int r = wm + mt * 16 + l4;
            int c = wn + nt * 8 + l2;
            float v0 = acc[mt][nt][0], v1 = acc[mt][nt][1];
            float v2 = acc[mt][nt][2], v3 = acc[mt][nt][3];
            if (mode == 2) {
                float b0 = d_bhhI[col0 + c], b1v = d_bhhI[col0 + c + 1];
                v0 += b0; v1 += b1v; v2 += b0; v3 += b1v;
                *(float2*)(ghOut + (size_t)(row0 + r) * H3 + col0 + c) =
                    make_float2(v0, v1);
                *(float2*)(ghOut + (size_t)(row0 + r + 8) * H3 + col0 + c) =
                    make_float2(v2, v3);
            }
            *(float2*)(st + r * 100 + c)       = make_float2(v0, v1);
            *(float2*)(st + (r + 8) * 100 + c) = make_float2(v2, v3);
        }
    }
    __syncthreads();

    // ---- GRU epilogue ----
    const int kbase = col0 / 3;
#pragma unroll
    for (int i = 0; i < 16; i++) {
        const int e = (i << 8) + t;
        const int r = e >> 5, kk = e & 31;
        const int grow = row0 + r;
        const int gk = kbase + kk;
        const int cc = kk * 3;
        float a0, a1, a2, g0, g1, g2;
        if (mode == 1) {
            a0 = st[r * 100 + cc + 0] + d_bihI[col0 + cc + 0];
            a1 = st[r * 100 + cc + 1] + d_bihI[col0 + cc + 1];
            a2 = st[r * 100 + cc + 2] + d_bihI[col0 + cc + 2];
            const float* gh = ghOld + (size_t)grow * H3 + col0 + cc;
            g0 = gh[0]; g1 = gh[1]; g2 = gh[2];
        } else {
            a0 = d_bihI[col0 + cc + 0];
            a1 = d_bihI[col0 + cc + 1];
            a2 = d_bihI[col0 + cc + 2];
            g0 = st[r * 100 + cc + 0];
            g1 = st[r * 100 + cc + 1];
            g2 = st[r * 100 + cc + 2];
        }
        float rr = sigm(a0 + g0);
        float zz = sigm(a1 + g1);
        float nn = tanhf(a2 + rr * g2);
        size_t hi = (size_t)grow * Cn + gk;
        float h = (1.f - zz) * nn + zz * hrun[hi];
        if (mode == 1) hrun[hi] = h;
        oH[hi] = __float2half_rn(h);
    }
}

// ---------------- fp32 32x128 GEMM (precompute only) ----------------
__global__ void __launch_bounds__(128)
gemm32(const float* __restrict__ A, const float* __restrict__ B,
       const float* __restrict__ bias, float* __restrict__ Cmat,
       int lda, int ldb, int ldc, int K, int relu)
{
    __shared__ float As[2][16][32];
    __shared__ float Bs[2][16][128];
    const int row0 = blockIdx.y * 32;
    const int col0 = blockIdx.x * 128;
    const int t  = threadIdx.x;
    const int ar = t >> 2;
    const int ak = (t & 3) * 4;
    const int tm = t >> 4;
    const int tn = t & 15;

    ull acc[4][4];
#pragma unroll
    for (int i = 0; i < 4; i++)
#pragma unroll
        for (int j = 0; j < 4; j++) acc[i][j] = 0ull;

    const float* Aptr = A + (size_t)(row0 + ar) * lda + ak;

    {
        float4 av = *(const float4*)(Aptr);
        As[0][ak+0][ar]=av.x; As[0][ak+1][ar]=av.y; As[0][ak+2][ar]=av.z; As[0][ak+3][ar]=av.w;
#pragma unroll
        for (int i2 = 0; i2 < 4; i2++) {
            int idx = t + 128 * i2;
            int br = idx >> 2, bk = (idx & 3) * 4;
            float4 bv = *(const float4*)(B + (size_t)(col0 + br) * ldb + bk);
            Bs[0][bk+0][br]=bv.x; Bs[0][bk+1][br]=bv.y; Bs[0][bk+2][br]=bv.z; Bs[0][bk+3][br]=bv.w;
        }
    }
    __syncthreads();

    int buf = 0;
    for (int k0 = 0; k0 < K; k0 += 16) {
        const bool more = (k0 + 16) < K;
        float4 an; float4 bn[4];
        if (more) {
            an = *(const float4*)(Aptr + k0 + 16);
#pragma unroll
            for (int i2 = 0; i2 < 4; i2++) {
                int idx = t + 128 * i2;
                int br = idx >> 2, bk = (idx & 3) * 4;
                bn[i2] = *(const float4*)(B + (size_t)(col0 + br) * ldb + k0 + 16 + bk);
            }
        }
#pragma unroll
        for (int kk = 0; kk < 16; kk++) {
            float av4[4];
            *(float4*)(av4) = *(const float4*)(&As[buf][kk][tm * 4]);
            ulonglong2 bv0 = *(const ulonglong2*)(&Bs[buf][kk][tn * 4]);
            ulonglong2 bv1 = *(const ulonglong2*)(&Bs[buf][kk][tn * 4 + 64]);
#pragma unroll
            for (int i = 0; i < 4; i++) {
                ull ap = pack2(av4[i]);
                ffma2(acc[i][0], ap, bv0.x);
                ffma2(acc[i][1], ap, bv0.y);
                ffma2(acc[i][2], ap, bv1.x);
                ffma2(acc[i][3], ap, bv1.y);
            }
        }
        if (more) {
            int nb = buf ^ 1;
            As[nb][ak+0][ar]=an.x; As[nb][ak+1][ar]=an.y; As[nb][ak+2][ar]=an.z; As[nb][ak+3][ar]=an.w;
#pragma unroll
            for (int i2 = 0; i2 < 4; i2++) {
                int idx = t + 128 * i2;
                int br = idx >> 2, bk = (idx & 3) * 4;
                Bs[nb][bk+0][br]=bn[i2].x; Bs[nb][bk+1][br]=bn[i2].y;
                Bs[nb][bk+2][br]=bn[i2].z; Bs[nb][bk+3][br]=bn[i2].w;
            }
        }
        __syncthreads();
        buf ^= 1;
    }
#pragma unroll
    for (int i = 0; i < 4; i++) {
        int r = row0 + tm * 4 + i;
        float* crow = Cmat + (size_t)r * ldc;
#pragma unroll
        for (int jp = 0; jp < 4; jp++) {
            int c = col0 + ((jp < 2) ? (tn * 4 + jp * 2) : (64 + tn * 4 + (jp - 2) * 2));
            float2 v = unpack2(acc[i][jp]);
            if (bias) { v.x += bias[c]; v.y += bias[c + 1]; }
            if (relu) { v.x = fmaxf(v.x, 0.f); v.y = fmaxf(v.y, 0.f); }
            *(float2*)(crow + c) = v;
        }
    }
}

// ---------------- elementwise / prep kernels ----------------
__global__ void k_copy_x0(const float* __restrict__ x) {
    int idx = blockIdx.x * 256 + threadIdx.x;
    int n = idx / Dn, d = idx - n * Dn;
    int g = n >> 4, p = n & 15;
    d_xb_h[idx] = __float2half_rn(x[((size_t)g * Sn * Pn + p) * Dn + d]);
}
__global__ void k_zero_hrun() {
    int idx = blockIdx.x * 256 + threadIdx.x;
    d_hrun[idx] = 0.f;
}
__global__ void k_bias_il(const float* __restrict__ bih, const float* __restrict__ bhh) {
    int idx = blockIdx.x * 256 + threadIdx.x;
    if (idx < H3) {
        int g = idx / 256, k = idx % 256;
        d_bihI[3 * k + g] = bih[idx];
        d_bhhI[3 * k + g] = bhh[idx];
    }
}
__global__ void k_init_gh2() {
    int idx = blockIdx.x * 256 + threadIdx.x;
    d_gh2[idx] = d_bhhI[idx % H3];
}
__global__ void k_speff(const float* __restrict__ spW) {
    int idx = blockIdx.x * 256 + threadIdx.x;
    int n = idx / Dn, d = idx - n * Dn;
    d_spWeff[idx] = spW[(size_t)n * 1536 + d] + spW[(size_t)n * 1536 + 768 + d];
}
__global__ void k_tr_gat(const float* __restrict__ gw) {
    int idx = blockIdx.x * 256 + threadIdx.x;
    int o = idx / Dn, d = idx - o * Dn;
    float v = gw[(size_t)d * HO + o];
    d_gatWT[idx] = v;
    d_gw_h[idx] = __float2half_rn(v);
}
__global__ void k_tr_up(const float* __restrict__ uw) {
    int idx = blockIdx.x * 256 + threadIdx.x;
    int c = idx / Dn, d = idx - c * Dn;
    d_upWT[idx] = uw[(size_t)d * Cn + c];
}
__global__ void k_b1(const float* __restrict__ sp_b, const float* __restrict__ up_b) {
    int n = blockIdx.x, lane = threadIdx.x;
    float s = 0.f;
    for (int d = lane; d < Dn; d += 32) s += d_spWeff[(size_t)n * Dn + d] * up_b[d];
#pragma unroll
    for (int off = 16; off; off >>= 1) s += __shfl_down_sync(0xffffffffu, s, off);
    if (lane == 0) d_b1[n] = s + sp_b[n];
}
__global__ void k_bg2(const float* __restrict__ up_b) {
    int o = blockIdx.x, lane = threadIdx.x;
    float s = 0.f;
    for (int d = lane; d < Dn; d += 32) s += d_gatWT[(size_t)o * Dn + d] * up_b[d];
#pragma unroll
    for (int off = 16; off; off >>= 1) s += __shfl_down_sync(0xffffffffu, s, off);
    if (lane == 0) d_bg2[o] = s;
}
__global__ void k_roundw(const float* __restrict__ w, hf* __restrict__ hi) {
    int idx = blockIdx.x * 256 + threadIdx.x;
    hi[idx] = __float2half_rn(w[idx]);
}
__global__ void k_roundw_perm(const float* __restrict__ w, hf* __restrict__ hi) {
    int idx = blockIdx.x * 256 + threadIdx.x;
    int row = idx / Cn, col = idx - row * Cn;
    int g = row >> 8, k = row & 255;
    int p = 3 * k + g;
    hi[(size_t)p * Cn + col] = __float2half_rn(w[idx]);
}

// GlobalAttention pool + classifier (reads fp16 mem)
__global__ void __launch_bounds__(256)
k_pool(const float* __restrict__ attW, const float* __restrict__ attb,
       const float* __restrict__ clsW, const float* __restrict__ clsb,
       float* __restrict__ out)
{
    int sg = blockIdx.x;
    int s = sg >> 7, g = sg & 127;
    __shared__ float gate[Pn];
    __shared__ float pooled[Cn];
    const hf* base = d_mem + ((size_t)s * GP + g * Pn) * Cn;
    int t = threadIdx.x, warp = t >> 5, lane = t & 31;

    for (int p = warp; p < Pn; p += 8) {
        float sum = 0.f;
        for (int c = lane; c < Cn; c += 32)
            sum += __half2float(base[p * Cn + c]) * attW[c];
#pragma unroll
        for (int off = 16; off; off >>= 1) sum += __shfl_down_sync(0xffffffffu, sum, off);
        if (lane == 0) gate[p] = sum + attb[0];
    }
    __syncthreads();
    if (t == 0) {
        float mx = -1e30f;
        for (int p = 0; p < Pn; p++) mx = fmaxf(mx, gate[p]);
        float den = 0.f, e[Pn];
        for (int p = 0; p < Pn; p++) { e[p] = expf(gate[p] - mx); den += e[p]; }
        float inv = 1.f / den;
        for (int p = 0; p < Pn; p++) gate[p] = e[p] * inv;
    }
    __syncthreads();
    {
        float acc = 0.f;
        for (int p = 0; p < Pn; p++)
            acc += gate[p] * __half2float(base[p * Cn + t]);
        pooled[t] = acc;
    }
    __syncthreads();
    if (warp < OUTn) {
        float sum = 0.f;
        for (int c = lane; c < Cn; c += 32) sum += pooled[c] * clsW[warp * Cn + c];
#pragma unroll
        for (int off = 16; off; off >>= 1) sum += __shfl_down_sync(0xffffffffu, sum, off);
        if (lane == 0) out[((size_t)g * Sn + s) * OUTn + warp] = sum + clsb[warp];
    }
}

// ---------------- host launcher ----------------
static inline void g32(const float* A, const float* B, const float* b, float* C,
                       int lda, int ldb, int ldc, int M, int N, int K, int relu)
{
    dim3 grid(N / 128, M / 32);
    gemm32<<<grid, 128>>>(A, B, b, C, lda, ldb, ldc, K, relu);
}

extern "C" void kernel_launch(void* const* d_in, const int* in_sizes, int n_in,
                              void* d_out, int out_size)
{
    const float* x      = (const float*)d_in[0];
    const float* gat_W  = (const float*)d_in[1];
    const float* att_src= (const float*)d_in[2];
    const float* att_dst= (const float*)d_in[3];
    const float* gat_b  = (const float*)d_in[4];
    const float* Wih    = (const float*)d_in[5];
    const float* Whh    = (const float*)d_in[6];
    const float* bih    = (const float*)d_in[7];
    const float* bhh    = (const float*)d_in[8];
    const float* up_W   = (const float*)d_in[9];
    const float* up_b   = (const float*)d_in[10];
    const float* sp_W   = (const float*)d_in[11];
    const float* sp_b   = (const float*)d_in[12];
    const float* attW   = (const float*)d_in[13];
    const float* attb   = (const float*)d_in[14];
    const float* clsW   = (const float*)d_in[15];
    const float* clsb   = (const float*)d_in[16];
    float* out = (float*)d_out;

    float *gh2, *spWeff, *gatWT, *upWT, *upgat, *Wsp, *b1, *bg2, *hrun;
    hf *mem, *hgat;
    cudaGetSymbolAddress((void**)&mem,   d_mem);
    cudaGetSymbolAddress((void**)&gh2,   d_gh2);
    cudaGetSymbolAddress((void**)&hgat,  d_hgat);
    cudaGetSymbolAddress((void**)&spWeff,d_spWeff);
    cudaGetSymbolAddress((void**)&gatWT, d_gatWT);
    cudaGetSymbolAddress((void**)&upWT,  d_upWT);
    cudaGetSymbolAddress((void**)&upgat, d_upgat);
    cudaGetSymbolAddress((void**)&Wsp,   d_Wsp);
    cudaGetSymbolAddress((void**)&b1,    d_b1);
    cudaGetSymbolAddress((void**)&bg2,   d_bg2);
    cudaGetSymbolAddress((void**)&hrun,  d_hrun);

    hf *Wih_h, *Whh_h, *ug_h, *Wsp_h, *gw_h, *xb_h;
    hf *hr_h, *hn_h, *spk_h;
    cudaGetSymbolAddress((void**)&Wih_h, d_Wih_h);
    cudaGetSymbolAddress((void**)&Whh_h, d_Whh_h);
    cudaGetSymbolAddress((void**)&ug_h,  d_ug_h);
    cudaGetSymbolAddress((void**)&Wsp_h, d_Wsp_h);
    cudaGetSymbolAddress((void**)&gw_h,  d_gw_h);
    cudaGetSymbolAddress((void**)&xb_h,  d_xb_h);
    cudaGetSymbolAddress((void**)&hr_h,  d_hr_h);
    cudaGetSymbolAddress((void**)&hn_h,  d_hn_h);
    cudaGetSymbolAddress((void**)&spk_h, d_spk_h);

    static bool attr_set = false;
    if (!attr_set) {
        cudaFuncSetAttribute(mma_gemm, cudaFuncAttributeMaxDynamicSharedMemorySize, MM_DSM);
        cudaFuncSetAttribute(k_spk_hgat, cudaFuncAttributeMaxDynamicSharedMemorySize, MM_DSM);
        cudaFuncSetAttribute(mma_gru, cudaFuncAttributeMaxDynamicSharedMemorySize, GRU_DSM);
        cudaFuncSetAttribute(mma_skinny, cudaFuncAttributeMaxDynamicSharedMemorySize, 12288);
        attr_set = true;
    }

    // ---- prep ----
    k_copy_x0<<<GP * Dn / 256, 256>>>(x);
    k_zero_hrun<<<GP * Cn / 256, 256>>>();
    k_bias_il<<<3, 256>>>(bih, bhh);
    k_init_gh2<<<GP * H3 / 256, 256>>>();
    k_speff<<<Dn * Dn / 256, 256>>>(sp_W);
    k_tr_gat<<<HO * Dn / 256, 256>>>(gat_W);
    k_tr_up<<<Cn * Dn / 256, 256>>>(up_W);
    k_b1<<<Dn, 32>>>(sp_b, up_b);
    k_bg2<<<HO, 32>>>(up_b);
    g32(gatWT, upWT, nullptr, upgat, Dn, Dn, Cn, HO, Cn, Dn, 0);
    g32(spWeff, upWT, nullptr, Wsp, Dn, Dn, Cn, Dn, Cn, Dn, 0);
    k_roundw_perm<<<H3 * Cn / 256, 256>>>(Wih, Wih_h);
    k_roundw_perm<<<H3 * Cn / 256, 256>>>(Whh, Whh_h);
    k_roundw<<<HO * Cn / 256, 256>>>(upgat, ug_h);
    k_roundw<<<Dn * Cn / 256, 256>>>(Wsp, Wsp_h);

    // ---- m0: GAT on x[:,0] (HMMA, K=768, fp16 hgat out) ----
    mma_gemm<<<dim3(8, 16), 256, MM_DSM>>>(
        xb_h, Dn, gw_h, Dn, nullptr, nullptr, 0, hgat, HO, Dn);
    k_gat_epi<<<Gn, 256>>>(att_src, att_dst, gat_b, mem);

    // ---- 31 sequential steps (5 launches each) ----
    for (int s = 1; s < Sn; s++) {
        // gru1: A = previous mem slice (fp16)
        mma_gru<<<dim3(8, 16), 256, GRU_DSM>>>(
            mem + (size_t)(s - 1) * GP * Cn, Cn, Wih_h,
            gh2, nullptr, hrun, hr_h, 1);
        mma_gru<<<dim3(8, 16), 256, GRU_DSM>>>(
            hr_h, Cn, Whh_h, nullptr, gh2, hrun, hn_h, 2);
        k_spk_hgat<<<176, 256, MM_DSM>>>(
            hn_h, ug_h, bg2, hgat, Wsp_h, b1, spk_h);
        mma_skinny<<<dim3(16, 4), 256, 12288>>>(
            spk_h, Dn, gw_h, Dn, nullptr,
            nullptr, 0, hgat, Pn * HO, Dn, 0);
        k_gat_epi<<<Gn, 256>>>(att_src, att_dst, gat_b,
                               mem + (size_t)s * GP * Cn);
    }

    // ---- pool + classify ----
    k_pool<<<Sn * Gn, 256>>>(attW, attb, clsW, clsb, out);
    (void)in_sizes; (void)n_in; (void)out_size;
}